// round 7
// baseline (speedup 1.0000x reference)
#include <cuda_runtime.h>
#include <cstdint>
#include <math_constants.h>

#define NN   1024
#define BB   128
#define SPLITK 16
#define KS   (NN / SPLITK)   // 64 k per block
#define BK   32              // k chunk in smem
#define BM   64              // b tile
#define BN   128             // j tile
#define XS_STRIDE 68
#define NTILES ((BB / BM) * (NN / BN))   // 16

// split-K partials: [SPLITK][BB][NN] = 8 MB (plain stores, cheap publish)
__device__ float g_partials[SPLITK * BB * NN];
// arrival counters per tile (zero-init; reset by 16th finisher each launch)
__device__ unsigned int g_cnt[NTILES];
__device__ unsigned int g_cnt2[NTILES];

__device__ __forceinline__ void cp_async16(uint32_t dst_smem, const void* src) {
    asm volatile("cp.async.cg.shared.global [%0], [%1], 16;\n"
                 :: "r"(dst_smem), "l"(src));
}
__device__ __forceinline__ void cp_commit() {
    asm volatile("cp.async.commit_group;\n" ::: "memory");
}
__device__ __forceinline__ void cp_wait0() {
    asm volatile("cp.async.wait_group 0;\n" ::: "memory");
}

__global__ void __launch_bounds__(256, 2)
tropical_fused(const float* __restrict__ x,
               const float* __restrict__ w,
               const float* __restrict__ bias,
               float* __restrict__ out)
{
    __shared__ float xs[BK][XS_STRIDE];     // x transposed: [k][b]  (8.7KB)
    __shared__ float ws[2][BK][BN];         // w natural:    [k][j]  (32.8KB)

    const int tid = threadIdx.x;
    const int tx  = tid & 15;
    const int ty  = tid >> 4;
    const int j0  = blockIdx.x * BN;
    const int b0  = blockIdx.y * BM;
    const int k0  = blockIdx.z * KS;
    const int tile = blockIdx.y * (NN / BN) + blockIdx.x;   // 0..15

    const int xb  = tid >> 3;              // 0..31 (+32)
    const int xk4 = (tid & 7) << 2;        // 0..28 step 4
    const int wrow = tid >> 5;             // 0..7 (+8h)
    const int wc4  = (tid & 31) << 2;      // 0..124 step 4

    float acc[4][8];
    #pragma unroll
    for (int r = 0; r < 4; r++)
        #pragma unroll
        for (int c = 0; c < 8; c++)
            acc[r][c] = -CUDART_INF_F;

    // ---- prologue: chunk 0 -> xs + ws[0] ----
    {
        #pragma unroll
        for (int h = 0; h < 2; h++) {
            const int bb = xb + 32 * h;
            float4 xr = *reinterpret_cast<const float4*>(&x[(b0 + bb) * NN + k0 + xk4]);
            xs[xk4 + 0][bb] = xr.x;
            xs[xk4 + 1][bb] = xr.y;
            xs[xk4 + 2][bb] = xr.z;
            xs[xk4 + 3][bb] = xr.w;
        }
        #pragma unroll
        for (int h = 0; h < 4; h++) {
            const int kr = wrow + 8 * h;
            uint32_t d = (uint32_t)__cvta_generic_to_shared(&ws[0][kr][wc4]);
            cp_async16(d, &w[(k0 + kr) * NN + j0 + wc4]);
        }
        cp_commit();
        cp_wait0();
        __syncthreads();
    }

    // ---- prefetch chunk 1: x into regs, ws via cp.async ----
    float4 xn0, xn1;
    {
        const int kb = k0 + BK;
        xn0 = *reinterpret_cast<const float4*>(&x[(b0 + xb) * NN + kb + xk4]);
        xn1 = *reinterpret_cast<const float4*>(&x[(b0 + xb + 32) * NN + kb + xk4]);
        #pragma unroll
        for (int h = 0; h < 4; h++) {
            const int kr = wrow + 8 * h;
            uint32_t d = (uint32_t)__cvta_generic_to_shared(&ws[1][kr][wc4]);
            cp_async16(d, &w[(kb + kr) * NN + j0 + wc4]);
        }
        cp_commit();
    }

    const int jq = tx << 2;

    // ---- compute chunk 0 ----
    #pragma unroll 16
    for (int k = 0; k < BK; k++) {
        float4 xv = *reinterpret_cast<const float4*>(&xs[k][ty << 2]);
        float4 w0 = *reinterpret_cast<const float4*>(&ws[0][k][jq]);
        float4 w1 = *reinterpret_cast<const float4*>(&ws[0][k][64 + jq]);
        float xr4[4] = {xv.x, xv.y, xv.z, xv.w};
        float wl[8]  = {w0.x, w0.y, w0.z, w0.w, w1.x, w1.y, w1.z, w1.w};
        #pragma unroll
        for (int r = 0; r < 4; r++)
            #pragma unroll
            for (int c = 0; c < 8; c++)
                acc[r][c] = fmaxf(acc[r][c], xr4[r] - wl[c]);
    }

    // ---- drain readers, stage x chunk 1 ----
    __syncthreads();
    xs[xk4 + 0][xb] = xn0.x;
    xs[xk4 + 1][xb] = xn0.y;
    xs[xk4 + 2][xb] = xn0.z;
    xs[xk4 + 3][xb] = xn0.w;
    xs[xk4 + 0][xb + 32] = xn1.x;
    xs[xk4 + 1][xb + 32] = xn1.y;
    xs[xk4 + 2][xb + 32] = xn1.z;
    xs[xk4 + 3][xb + 32] = xn1.w;
    cp_wait0();
    __syncthreads();

    // ---- compute chunk 1 ----
    #pragma unroll 16
    for (int k = 0; k < BK; k++) {
        float4 xv = *reinterpret_cast<const float4*>(&xs[k][ty << 2]);
        float4 w0 = *reinterpret_cast<const float4*>(&ws[1][k][jq]);
        float4 w1 = *reinterpret_cast<const float4*>(&ws[1][k][64 + jq]);
        float xr4[4] = {xv.x, xv.y, xv.z, xv.w};
        float wl[8]  = {w0.x, w0.y, w0.z, w0.w, w1.x, w1.y, w1.z, w1.w};
        #pragma unroll
        for (int r = 0; r < 4; r++)
            #pragma unroll
            for (int c = 0; c < 8; c++)
                acc[r][c] = fmaxf(acc[r][c], xr4[r] - wl[c]);
    }

    // ---- publish partials (plain STG.128) ----
    float* p = &g_partials[blockIdx.z * (BB * NN)];
    #pragma unroll
    for (int r = 0; r < 4; r++) {
        const int row = (b0 + (ty << 2) + r) * NN + j0;
        float4 o0, o1;
        o0.x = acc[r][0]; o0.y = acc[r][1]; o0.z = acc[r][2]; o0.w = acc[r][3];
        o1.x = acc[r][4]; o1.y = acc[r][5]; o1.z = acc[r][6]; o1.w = acc[r][7];
        *reinterpret_cast<float4*>(&p[row + jq])      = o0;
        *reinterpret_cast<float4*>(&p[row + 64 + jq]) = o1;
    }

    // ---- arrive + spin until all 16 sibling blocks have published ----
    __threadfence();                 // make partials gpu-visible
    __syncthreads();
    if (tid == 0) {
        unsigned int old;
        asm volatile("atom.release.gpu.global.add.u32 %0, [%1], %2;"
                     : "=r"(old) : "l"(&g_cnt[tile]), "r"(1u) : "memory");
        unsigned int v = old + 1;
        while (v != SPLITK) {
            asm volatile("ld.acquire.gpu.global.u32 %0, [%1];"
                         : "=r"(v) : "l"(&g_cnt[tile]) : "memory");
        }
    }
    __syncthreads();                 // broadcast "all arrived" to block

    // ---- cooperative finalize: block z reduces rows [z*4, z*4+4) of tile ----
    // 4 rows x 128 cols = 128 float4; threads 0..127 take one each.
    if (tid < 128) {
        const int row = b0 + blockIdx.z * 4 + (tid >> 5);  // 4 rows per block
        const int col = j0 + ((tid & 31) << 2);
        const int idx = row * NN + col;
        float4 m = __ldcg(reinterpret_cast<const float4*>(&g_partials[idx]));
        #pragma unroll
        for (int s = 1; s < SPLITK; s++) {
            float4 q = __ldcg(reinterpret_cast<const float4*>(&g_partials[s * (BB * NN) + idx]));
            m.x = fmaxf(m.x, q.x);
            m.y = fmaxf(m.y, q.y);
            m.z = fmaxf(m.z, q.z);
            m.w = fmaxf(m.w, q.w);
        }
        float4 bv = *reinterpret_cast<const float4*>(&bias[col]);
        float4 o;
        o.x = m.x + bv.x;
        o.y = m.y + bv.y;
        o.z = m.z + bv.z;
        o.w = m.w + bv.w;
        *reinterpret_cast<float4*>(&out[idx]) = o;
    }

    // ---- reset counters for the next graph replay ----
    __syncthreads();
    if (tid == 0) {
        unsigned int old2;
        asm volatile("atom.release.gpu.global.add.u32 %0, [%1], %2;"
                     : "=r"(old2) : "l"(&g_cnt2[tile]), "r"(1u) : "memory");
        if (old2 == SPLITK - 1) {    // everyone passed the spin; safe to zero
            g_cnt[tile]  = 0;
            g_cnt2[tile] = 0;
        }
    }
}

extern "C" void kernel_launch(void* const* d_in, const int* in_sizes, int n_in,
                              void* d_out, int out_size) {
    const float* x    = (const float*)d_in[0];   // [128, 1024]
    const float* wgt  = (const float*)d_in[1];   // [1024, 1024]
    const float* bias = (const float*)d_in[2];   // [1024]
    float* out = (float*)d_out;                  // [128, 1024]

    dim3 grid(NN / BN, BB / BM, SPLITK);         // (8, 2, 16) = 256 blocks, one wave
    tropical_fused<<<grid, 256>>>(x, wgt, bias, out);
}

// round 8
// speedup vs baseline: 1.1016x; 1.1016x over previous
#include <cuda_runtime.h>
#include <cstdint>
#include <math_constants.h>

#define NN   1024
#define BB   128
#define SPLITK 16
#define KS   (NN / SPLITK)   // 64 k per block
#define BK   32              // k chunk in smem
#define BM   64              // b tile
#define BN   128             // j tile
#define XS_STRIDE 68

// split-K partials: [SPLITK][BB][NN] = 8 MB
__device__ float g_partials[SPLITK * BB * NN];

__device__ __forceinline__ void cp_async16(uint32_t dst_smem, const void* src) {
    asm volatile("cp.async.cg.shared.global [%0], [%1], 16;\n"
                 :: "r"(dst_smem), "l"(src));
}
__device__ __forceinline__ void cp_commit() {
    asm volatile("cp.async.commit_group;\n" ::: "memory");
}
__device__ __forceinline__ void cp_wait0() {
    asm volatile("cp.async.wait_group 0;\n" ::: "memory");
}

// x - w as a single FFMA on the fma pipe (exact: w * -1 + x)
__device__ __forceinline__ float sub_fma(float xv, float wv) {
    return __fmaf_rn(wv, -1.0f, xv);
}

__global__ void __launch_bounds__(256, 2)
tropical_main(const float* __restrict__ x,
              const float* __restrict__ w)
{
    __shared__ float xs[BK][XS_STRIDE];     // x transposed: [k][b]  (8.7KB)
    __shared__ float ws[2][BK][BN];         // w natural:    [k][j]  (32.8KB)

    const int tid = threadIdx.x;
    const int tx  = tid & 15;
    const int ty  = tid >> 4;
    const int j0  = blockIdx.x * BN;
    const int b0  = blockIdx.y * BM;
    const int k0  = blockIdx.z * KS;

    const int xb  = tid >> 3;              // 0..31 (+32)
    const int xk4 = (tid & 7) << 2;        // 0..28 step 4
    const int wrow = tid >> 5;             // 0..7 (+8h)
    const int wc4  = (tid & 31) << 2;      // 0..124 step 4

    float acc[4][8];
    #pragma unroll
    for (int r = 0; r < 4; r++)
        #pragma unroll
        for (int c = 0; c < 8; c++)
            acc[r][c] = -CUDART_INF_F;

    // ---- prologue: chunk 0 -> xs + ws[0] ----
    {
        #pragma unroll
        for (int h = 0; h < 2; h++) {
            const int bb = xb + 32 * h;
            float4 xr = *reinterpret_cast<const float4*>(&x[(b0 + bb) * NN + k0 + xk4]);
            xs[xk4 + 0][bb] = xr.x;
            xs[xk4 + 1][bb] = xr.y;
            xs[xk4 + 2][bb] = xr.z;
            xs[xk4 + 3][bb] = xr.w;
        }
        #pragma unroll
        for (int h = 0; h < 4; h++) {
            const int kr = wrow + 8 * h;
            uint32_t d = (uint32_t)__cvta_generic_to_shared(&ws[0][kr][wc4]);
            cp_async16(d, &w[(k0 + kr) * NN + j0 + wc4]);
        }
        cp_commit();
        cp_wait0();
        __syncthreads();
    }

    // ---- prefetch chunk 1: x into regs, ws via cp.async ----
    float4 xn0, xn1;
    {
        const int kb = k0 + BK;
        xn0 = *reinterpret_cast<const float4*>(&x[(b0 + xb) * NN + kb + xk4]);
        xn1 = *reinterpret_cast<const float4*>(&x[(b0 + xb + 32) * NN + kb + xk4]);
        #pragma unroll
        for (int h = 0; h < 4; h++) {
            const int kr = wrow + 8 * h;
            uint32_t d = (uint32_t)__cvta_generic_to_shared(&ws[1][kr][wc4]);
            cp_async16(d, &w[(kb + kr) * NN + j0 + wc4]);
        }
        cp_commit();
    }

    const int jq = tx << 2;
    const int bq = ty << 2;

    // ---- compute chunk 0 (software-pipelined: load k+1 before computing k) ----
    {
        float4 xv = *reinterpret_cast<const float4*>(&xs[0][bq]);
        float4 w0 = *reinterpret_cast<const float4*>(&ws[0][0][jq]);
        float4 w1 = *reinterpret_cast<const float4*>(&ws[0][0][64 + jq]);
        #pragma unroll
        for (int k = 0; k < BK; k++) {
            float4 xv_n, w0_n, w1_n;
            if (k + 1 < BK) {
                xv_n = *reinterpret_cast<const float4*>(&xs[k + 1][bq]);
                w0_n = *reinterpret_cast<const float4*>(&ws[0][k + 1][jq]);
                w1_n = *reinterpret_cast<const float4*>(&ws[0][k + 1][64 + jq]);
            }
            float xr4[4] = {xv.x, xv.y, xv.z, xv.w};
            float wl[8]  = {w0.x, w0.y, w0.z, w0.w, w1.x, w1.y, w1.z, w1.w};
            #pragma unroll
            for (int r = 0; r < 4; r++)
                #pragma unroll
                for (int c = 0; c < 8; c++)
                    acc[r][c] = fmaxf(acc[r][c], sub_fma(xr4[r], wl[c]));
            xv = xv_n; w0 = w0_n; w1 = w1_n;
        }
    }

    // ---- drain readers, stage x chunk 1 ----
    __syncthreads();
    xs[xk4 + 0][xb] = xn0.x;
    xs[xk4 + 1][xb] = xn0.y;
    xs[xk4 + 2][xb] = xn0.z;
    xs[xk4 + 3][xb] = xn0.w;
    xs[xk4 + 0][xb + 32] = xn1.x;
    xs[xk4 + 1][xb + 32] = xn1.y;
    xs[xk4 + 2][xb + 32] = xn1.z;
    xs[xk4 + 3][xb + 32] = xn1.w;
    cp_wait0();
    __syncthreads();

    // ---- compute chunk 1 (same pipelined body) ----
    {
        float4 xv = *reinterpret_cast<const float4*>(&xs[0][bq]);
        float4 w0 = *reinterpret_cast<const float4*>(&ws[1][0][jq]);
        float4 w1 = *reinterpret_cast<const float4*>(&ws[1][0][64 + jq]);
        #pragma unroll
        for (int k = 0; k < BK; k++) {
            float4 xv_n, w0_n, w1_n;
            if (k + 1 < BK) {
                xv_n = *reinterpret_cast<const float4*>(&xs[k + 1][bq]);
                w0_n = *reinterpret_cast<const float4*>(&ws[1][k + 1][jq]);
                w1_n = *reinterpret_cast<const float4*>(&ws[1][k + 1][64 + jq]);
            }
            float xr4[4] = {xv.x, xv.y, xv.z, xv.w};
            float wl[8]  = {w0.x, w0.y, w0.z, w0.w, w1.x, w1.y, w1.z, w1.w};
            #pragma unroll
            for (int r = 0; r < 4; r++)
                #pragma unroll
                for (int c = 0; c < 8; c++)
                    acc[r][c] = fmaxf(acc[r][c], sub_fma(xr4[r], wl[c]));
            xv = xv_n; w0 = w0_n; w1 = w1_n;
        }
    }

    // ---- write partials (plain STG.128) ----
    float* p = &g_partials[blockIdx.z * (BB * NN)];
    #pragma unroll
    for (int r = 0; r < 4; r++) {
        const int row = (b0 + bq + r) * NN + j0;
        float4 o0, o1;
        o0.x = acc[r][0]; o0.y = acc[r][1]; o0.z = acc[r][2]; o0.w = acc[r][3];
        o1.x = acc[r][4]; o1.y = acc[r][5]; o1.z = acc[r][6]; o1.w = acc[r][7];
        *reinterpret_cast<float4*>(&p[row + jq])      = o0;
        *reinterpret_cast<float4*>(&p[row + 64 + jq]) = o1;
    }
}

__global__ void __launch_bounds__(256, 8)
tropical_reduce(const float* __restrict__ bias,
                float* __restrict__ out)
{
    // float2 per thread, grid 256 blocks -> ~1.7 blocks/SM, occ 25%
    const int i = (blockIdx.x * 256 + threadIdx.x) << 1;
    float2 m = *reinterpret_cast<const float2*>(&g_partials[i]);
    #pragma unroll
    for (int s = 1; s < SPLITK; s++) {
        float2 q = *reinterpret_cast<const float2*>(&g_partials[s * (BB * NN) + i]);
        m.x = fmaxf(m.x, q.x);
        m.y = fmaxf(m.y, q.y);
    }
    const int j = i & (NN - 1);
    float2 bv = *reinterpret_cast<const float2*>(&bias[j]);
    float2 o;
    o.x = m.x + bv.x;
    o.y = m.y + bv.y;
    *reinterpret_cast<float2*>(&out[i]) = o;
}

extern "C" void kernel_launch(void* const* d_in, const int* in_sizes, int n_in,
                              void* d_out, int out_size) {
    const float* x    = (const float*)d_in[0];   // [128, 1024]
    const float* wgt  = (const float*)d_in[1];   // [1024, 1024]
    const float* bias = (const float*)d_in[2];   // [1024]
    float* out = (float*)d_out;                  // [128, 1024]

    dim3 grid(NN / BN, BB / BM, SPLITK);         // (8, 2, 16) = 256 blocks
    tropical_main<<<grid, 256>>>(x, wgt);

    const int total = BB * NN;                   // 131072
    tropical_reduce<<<total / 2 / 256, 256>>>(bias, out);   // 256 blocks
}

// round 9
// speedup vs baseline: 1.1595x; 1.0526x over previous
#include <cuda_runtime.h>
#include <cstdint>
#include <math_constants.h>

#define NN   1024
#define BB   128
#define SPLITK 16
#define KS   (NN / SPLITK)   // 64 k per block
#define BK   32              // k chunk in smem
#define BM   64              // b tile
#define BN   128             // j tile
#define XS_STRIDE 68
#define NT   512             // threads per block (16 warps)

// split-K partials: [SPLITK][BB][NN] = 8 MB
__device__ float g_partials[SPLITK * BB * NN];
// opaque -1.0f so ptxas cannot fold the FFMA back into FADD
__device__ float g_negone = -1.0f;

__device__ __forceinline__ void cp_async16(uint32_t dst_smem, const void* src) {
    asm volatile("cp.async.cg.shared.global [%0], [%1], 16;\n"
                 :: "r"(dst_smem), "l"(src));
}
__device__ __forceinline__ void cp_commit() {
    asm volatile("cp.async.commit_group;\n" ::: "memory");
}
__device__ __forceinline__ void cp_wait0() {
    asm volatile("cp.async.wait_group 0;\n" ::: "memory");
}

__global__ void __launch_bounds__(NT, 2)
tropical_main(const float* __restrict__ x,
              const float* __restrict__ w)
{
    __shared__ float xs[BK][XS_STRIDE];     // x transposed: [k][b]  (8.7KB)
    __shared__ float ws[2][BK][BN];         // w natural:    [k][j]  (32.8KB)

    const int tid = threadIdx.x;
    const int tx  = tid & 31;        // j group (0..31) -> 4 j each
    const int ty  = tid >> 5;        // b group (0..15) -> 4 b each (= warp id)
    const int j0  = blockIdx.x * BN;
    const int b0  = blockIdx.y * BM;
    const int k0  = blockIdx.z * KS;

    // x load mapping: 1 float4 per thread per chunk (64 rows x 32 k)
    const int xb  = tid >> 3;              // 0..63
    const int xk4 = (tid & 7) << 2;        // 0..28 step 4
    // ws load mapping: 2 cp16 per thread per chunk (32 rows x 128 j)
    const int wrow = tid >> 5;             // 0..15 (+16)
    const int wc4  = (tid & 31) << 2;      // 0..124 step 4

    const float negone = g_negone;         // runtime value -> real FFMA

    float acc[4][4];
    #pragma unroll
    for (int r = 0; r < 4; r++)
        #pragma unroll
        for (int c = 0; c < 4; c++)
            acc[r][c] = -CUDART_INF_F;

    // ---- prologue: chunk 0 -> xs + ws[0] ----
    {
        float4 xr = *reinterpret_cast<const float4*>(&x[(b0 + xb) * NN + k0 + xk4]);
        xs[xk4 + 0][xb] = xr.x;
        xs[xk4 + 1][xb] = xr.y;
        xs[xk4 + 2][xb] = xr.z;
        xs[xk4 + 3][xb] = xr.w;
        #pragma unroll
        for (int h = 0; h < 2; h++) {
            const int kr = wrow + 16 * h;
            uint32_t d = (uint32_t)__cvta_generic_to_shared(&ws[0][kr][wc4]);
            cp_async16(d, &w[(k0 + kr) * NN + j0 + wc4]);
        }
        cp_commit();
        cp_wait0();
        __syncthreads();
    }

    // ---- prefetch chunk 1: x into regs, ws via cp.async ----
    float4 xn;
    {
        const int kb = k0 + BK;
        xn = *reinterpret_cast<const float4*>(&x[(b0 + xb) * NN + kb + xk4]);
        #pragma unroll
        for (int h = 0; h < 2; h++) {
            const int kr = wrow + 16 * h;
            uint32_t d = (uint32_t)__cvta_generic_to_shared(&ws[1][kr][wc4]);
            cp_async16(d, &w[(kb + kr) * NN + j0 + wc4]);
        }
        cp_commit();
    }

    const int jq = tx << 2;   // 0..124 step 4
    const int bq = ty << 2;   // 0..60 step 4

    // ---- compute chunk 0 ----
    #pragma unroll
    for (int k = 0; k < BK; k++) {
        float4 xv = *reinterpret_cast<const float4*>(&xs[k][bq]);   // warp broadcast
        float4 wv = *reinterpret_cast<const float4*>(&ws[0][k][jq]);
        float xr4[4] = {xv.x, xv.y, xv.z, xv.w};
        float wl[4]  = {wv.x, wv.y, wv.z, wv.w};
        #pragma unroll
        for (int r = 0; r < 4; r++)
            #pragma unroll
            for (int c = 0; c < 4; c++)
                acc[r][c] = fmaxf(acc[r][c], __fmaf_rn(wl[c], negone, xr4[r]));
    }

    // ---- drain readers, stage x chunk 1 ----
    __syncthreads();
    xs[xk4 + 0][xb] = xn.x;
    xs[xk4 + 1][xb] = xn.y;
    xs[xk4 + 2][xb] = xn.z;
    xs[xk4 + 3][xb] = xn.w;
    cp_wait0();
    __syncthreads();

    // ---- compute chunk 1 ----
    #pragma unroll
    for (int k = 0; k < BK; k++) {
        float4 xv = *reinterpret_cast<const float4*>(&xs[k][bq]);
        float4 wv = *reinterpret_cast<const float4*>(&ws[1][k][jq]);
        float xr4[4] = {xv.x, xv.y, xv.z, xv.w};
        float wl[4]  = {wv.x, wv.y, wv.z, wv.w};
        #pragma unroll
        for (int r = 0; r < 4; r++)
            #pragma unroll
            for (int c = 0; c < 4; c++)
                acc[r][c] = fmaxf(acc[r][c], __fmaf_rn(wl[c], negone, xr4[r]));
    }

    // ---- write partials (plain STG.128) ----
    float* p = &g_partials[blockIdx.z * (BB * NN)];
    #pragma unroll
    for (int r = 0; r < 4; r++) {
        float4 o;
        o.x = acc[r][0]; o.y = acc[r][1]; o.z = acc[r][2]; o.w = acc[r][3];
        *reinterpret_cast<float4*>(&p[(b0 + bq + r) * NN + j0 + jq]) = o;
    }
}

__global__ void __launch_bounds__(256, 8)
tropical_reduce(const float* __restrict__ bias,
                float* __restrict__ out)
{
    // float2 per thread, 256 blocks
    const int i = (blockIdx.x * 256 + threadIdx.x) << 1;
    float2 m = *reinterpret_cast<const float2*>(&g_partials[i]);
    #pragma unroll
    for (int s = 1; s < SPLITK; s++) {
        float2 q = *reinterpret_cast<const float2*>(&g_partials[s * (BB * NN) + i]);
        m.x = fmaxf(m.x, q.x);
        m.y = fmaxf(m.y, q.y);
    }
    const int j = i & (NN - 1);
    float2 bv = *reinterpret_cast<const float2*>(&bias[j]);
    float2 o;
    o.x = m.x + bv.x;
    o.y = m.y + bv.y;
    *reinterpret_cast<float2*>(&out[i]) = o;
}

extern "C" void kernel_launch(void* const* d_in, const int* in_sizes, int n_in,
                              void* d_out, int out_size) {
    const float* x    = (const float*)d_in[0];   // [128, 1024]
    const float* wgt  = (const float*)d_in[1];   // [1024, 1024]
    const float* bias = (const float*)d_in[2];   // [1024]
    float* out = (float*)d_out;                  // [128, 1024]

    dim3 grid(NN / BN, BB / BM, SPLITK);         // (8, 2, 16) = 256 blocks
    tropical_main<<<grid, NT>>>(x, wgt);

    const int total = BB * NN;                   // 131072
    tropical_reduce<<<total / 2 / 256, 256>>>(bias, out);   // 256 blocks
}